// round 1
// baseline (speedup 1.0000x reference)
#include <cuda_runtime.h>
#include <math.h>

// Problem constants
constexpr int B_  = 4;
constexpr int T_  = 2048;
constexpr int D_  = 1024;
constexpr int H_  = 16;
constexpr int DH_ = 64;
constexpr int M_  = B_ * T_;   // 8192 rows
constexpr int N_  = D_;        // 1024
constexpr int K_  = D_;        // 1024

// Scratch (device globals: allocation-free per harness rules). 4 x 32 MB.
__device__ float g_q  [M_ * D_];
__device__ float g_k  [M_ * D_];
__device__ float g_v  [M_ * D_];
__device__ float g_ctx[M_ * D_];

// ---------------------------------------------------------------------------
// SGEMM body: C[M,N] = A[M,K] @ W[K,N] (+ bias). 128x128 tile, BK=8,
// 256 threads, 8x8 per thread. M,N,K are multiples of 128 -> no bounds checks.
// ---------------------------------------------------------------------------
__device__ __forceinline__ void sgemm_body(const float* __restrict__ A,
                                           const float* __restrict__ W,
                                           float* __restrict__ C,
                                           const float* __restrict__ bias) {
    __shared__ float As[8][128];
    __shared__ float Bs[8][128];

    const int t  = threadIdx.x;
    const int r0 = blockIdx.y * 128;
    const int c0 = blockIdx.x * 128;
    const int tx = t & 15;        // 0..15
    const int ty = t >> 4;        // 0..15

    const int arow  = t >> 1;           // 0..127
    const int acol4 = (t & 1) * 4;      // 0 or 4
    const int brow  = t >> 5;           // 0..7
    const int bcol4 = (t & 31) * 4;     // 0..124

    float acc[8][8];
#pragma unroll
    for (int i = 0; i < 8; ++i)
#pragma unroll
        for (int j = 0; j < 8; ++j) acc[i][j] = 0.f;

    for (int k0 = 0; k0 < K_; k0 += 8) {
        float4 av = *reinterpret_cast<const float4*>(
            &A[(size_t)(r0 + arow) * K_ + k0 + acol4]);
        float4 bv = *reinterpret_cast<const float4*>(
            &W[(size_t)(k0 + brow) * N_ + c0 + bcol4]);

        As[acol4 + 0][arow] = av.x;
        As[acol4 + 1][arow] = av.y;
        As[acol4 + 2][arow] = av.z;
        As[acol4 + 3][arow] = av.w;
        *reinterpret_cast<float4*>(&Bs[brow][bcol4]) = bv;
        __syncthreads();

#pragma unroll
        for (int kk = 0; kk < 8; ++kk) {
            float ra[8], rb[8];
            *reinterpret_cast<float4*>(&ra[0]) =
                *reinterpret_cast<const float4*>(&As[kk][ty * 8]);
            *reinterpret_cast<float4*>(&ra[4]) =
                *reinterpret_cast<const float4*>(&As[kk][ty * 8 + 4]);
            *reinterpret_cast<float4*>(&rb[0]) =
                *reinterpret_cast<const float4*>(&Bs[kk][tx * 8]);
            *reinterpret_cast<float4*>(&rb[4]) =
                *reinterpret_cast<const float4*>(&Bs[kk][tx * 8 + 4]);
#pragma unroll
            for (int i = 0; i < 8; ++i)
#pragma unroll
                for (int j = 0; j < 8; ++j)
                    acc[i][j] += ra[i] * rb[j];
        }
        __syncthreads();
    }

#pragma unroll
    for (int i = 0; i < 8; ++i) {
        const size_t row = (size_t)(r0 + ty * 8 + i);
#pragma unroll
        for (int j = 0; j < 8; j += 4) {
            float4 v;
            v.x = acc[i][j + 0];
            v.y = acc[i][j + 1];
            v.z = acc[i][j + 2];
            v.w = acc[i][j + 3];
            if (bias) {
                const int c = c0 + tx * 8 + j;
                v.x += bias[c + 0]; v.y += bias[c + 1];
                v.z += bias[c + 2]; v.w += bias[c + 3];
            }
            *reinterpret_cast<float4*>(&C[row * N_ + c0 + tx * 8 + j]) = v;
        }
    }
}

// QKV projections: grid.z selects Wq/Wk/Wv -> g_q/g_k/g_v ([B,T,D] layout).
__global__ __launch_bounds__(256, 2)
void sgemm_qkv(const float* __restrict__ x,
               const float* __restrict__ Wq,
               const float* __restrict__ Wk,
               const float* __restrict__ Wv) {
    const float* W = (blockIdx.z == 0) ? Wq : (blockIdx.z == 1) ? Wk : Wv;
    float* C = (blockIdx.z == 0) ? g_q : (blockIdx.z == 1) ? g_k : g_v;
    sgemm_body(x, W, C, nullptr);
}

// Output projection: out = g_ctx @ Wo + bo
__global__ __launch_bounds__(256, 2)
void sgemm_out(const float* __restrict__ Wo,
               const float* __restrict__ bo,
               float* __restrict__ out) {
    sgemm_body(g_ctx, Wo, out, bo);
}

// ---------------------------------------------------------------------------
// Flash attention (causal). One block = (b, h, 128 q-rows); 128 threads,
// thread owns one q row entirely (q[64], o[64] in registers). K/V tiles of 64
// staged in smem; online softmax updated in 16-key chunks.
// ---------------------------------------------------------------------------
constexpr int BQ  = 128;
constexpr int BKV = 64;
constexpr int QS_STRIDE = 68;  // pad row to avoid bank conflicts on strided LDS

template <int CN>
__device__ __forceinline__ void attn_chunk(const float* __restrict__ Ks,
                                           const float* __restrict__ Vs,
                                           int c,
                                           const float (&q)[64],
                                           float (&o)[64],
                                           float& m, float& l) {
    float s[CN];
    float mloc = m;
#pragma unroll
    for (int jj = 0; jj < CN; ++jj) {
        const float4* kr = reinterpret_cast<const float4*>(&Ks[(c + jj) * 64]);
        float acc = 0.f;
#pragma unroll
        for (int d4 = 0; d4 < 16; ++d4) {
            float4 kv = kr[d4];
            acc += q[d4 * 4 + 0] * kv.x;
            acc += q[d4 * 4 + 1] * kv.y;
            acc += q[d4 * 4 + 2] * kv.z;
            acc += q[d4 * 4 + 3] * kv.w;
        }
        s[jj] = acc * 0.125f;   // 1/sqrt(64)
        mloc = fmaxf(mloc, s[jj]);
    }
    if (mloc > m) {
        const float alpha = __expf(m - mloc);   // m0=-1e30 -> alpha==0
        l *= alpha;
#pragma unroll
        for (int d = 0; d < 64; ++d) o[d] *= alpha;
        m = mloc;
    }
#pragma unroll
    for (int jj = 0; jj < CN; ++jj) {
        const float p = __expf(s[jj] - m);
        l += p;
        const float4* vr = reinterpret_cast<const float4*>(&Vs[(c + jj) * 64]);
#pragma unroll
        for (int d4 = 0; d4 < 16; ++d4) {
            float4 vv = vr[d4];
            o[d4 * 4 + 0] += p * vv.x;
            o[d4 * 4 + 1] += p * vv.y;
            o[d4 * 4 + 2] += p * vv.z;
            o[d4 * 4 + 3] += p * vv.w;
        }
    }
}

__global__ __launch_bounds__(128, 3)
void flash_attn() {
    extern __shared__ float sm[];
    float* Qs = sm;                          // BQ * QS_STRIDE floats
    float* Ks = sm + BQ * QS_STRIDE;         // BKV * 64
    float* Vs = Ks + BKV * 64;               // BKV * 64

    const int t  = threadIdx.x;
    const int h  = blockIdx.y;
    const int b  = blockIdx.z;
    const int q0 = blockIdx.x * BQ;
    const size_t base = (size_t)b * T_ * D_ + (size_t)h * DH_;

    // Cooperative, coalesced Q-tile load -> smem -> registers
    for (int idx = t; idx < BQ * 16; idx += 128) {
        const int r = idx >> 4, c4 = (idx & 15) * 4;
        *reinterpret_cast<float4*>(&Qs[r * QS_STRIDE + c4]) =
            *reinterpret_cast<const float4*>(&g_q[base + (size_t)(q0 + r) * D_ + c4]);
    }
    __syncthreads();

    float q[64];
#pragma unroll
    for (int d4 = 0; d4 < 16; ++d4) {
        float4 v = *reinterpret_cast<const float4*>(&Qs[t * QS_STRIDE + d4 * 4]);
        q[d4 * 4 + 0] = v.x; q[d4 * 4 + 1] = v.y;
        q[d4 * 4 + 2] = v.z; q[d4 * 4 + 3] = v.w;
    }

    float o[64];
#pragma unroll
    for (int d = 0; d < 64; ++d) o[d] = 0.f;
    float m = -1e30f, l = 0.f;

    const int tq     = q0 + t;
    const int ntiles = (q0 + BQ) / BKV;   // key tiles needed by this block

    for (int j = 0; j < ntiles; ++j) {
        // Load K/V tiles (coalesced float4)
        for (int idx = t; idx < BKV * 16; idx += 128) {
            const int r = idx >> 4, c4 = (idx & 15) * 4;
            const size_t g = base + (size_t)(j * BKV + r) * D_ + c4;
            *reinterpret_cast<float4*>(&Ks[r * 64 + c4]) =
                *reinterpret_cast<const float4*>(&g_k[g]);
            *reinterpret_cast<float4*>(&Vs[r * 64 + c4]) =
                *reinterpret_cast<const float4*>(&g_v[g]);
        }
        __syncthreads();

        int valid = tq - j * BKV + 1;     // causal: keys kg <= tq
        if (valid > BKV) valid = BKV;
        if (valid == BKV) {
#pragma unroll
            for (int c = 0; c < BKV; c += 16)
                attn_chunk<16>(Ks, Vs, c, q, o, m, l);
        } else if (valid > 0) {
            for (int c = 0; c < valid; ++c)
                attn_chunk<1>(Ks, Vs, c, q, o, m, l);
        }
        __syncthreads();
    }

    // Normalize and stage through smem for coalesced store
    const float inv = 1.f / l;
#pragma unroll
    for (int d4 = 0; d4 < 16; ++d4) {
        float4 v;
        v.x = o[d4 * 4 + 0] * inv; v.y = o[d4 * 4 + 1] * inv;
        v.z = o[d4 * 4 + 2] * inv; v.w = o[d4 * 4 + 3] * inv;
        *reinterpret_cast<float4*>(&Qs[t * QS_STRIDE + d4 * 4]) = v;
    }
    __syncthreads();
    for (int idx = t; idx < BQ * 16; idx += 128) {
        const int r = idx >> 4, c4 = (idx & 15) * 4;
        *reinterpret_cast<float4*>(&g_ctx[base + (size_t)(q0 + r) * D_ + c4]) =
            *reinterpret_cast<const float4*>(&Qs[r * QS_STRIDE + c4]);
    }
}

// ---------------------------------------------------------------------------
extern "C" void kernel_launch(void* const* d_in, const int* in_sizes, int n_in,
                              void* d_out, int out_size) {
    const float* x  = (const float*)d_in[0];
    const float* Wq = (const float*)d_in[1];
    const float* Wk = (const float*)d_in[2];
    const float* Wv = (const float*)d_in[3];
    const float* Wo = (const float*)d_in[4];
    const float* bo = (const float*)d_in[5];
    float* out = (float*)d_out;

    // 1) QKV projections
    dim3 gq(N_ / 128, M_ / 128, 3);
    sgemm_qkv<<<gq, 256>>>(x, Wq, Wk, Wv);

    // 2) Causal flash attention
    const size_t smem = (size_t)(BQ * QS_STRIDE + 2 * BKV * 64) * sizeof(float);
    cudaFuncSetAttribute(flash_attn,
                         cudaFuncAttributeMaxDynamicSharedMemorySize, (int)smem);
    flash_attn<<<dim3(T_ / BQ, H_, B_), 128, smem>>>();

    // 3) Output projection (+bias)
    sgemm_out<<<dim3(N_ / 128, M_ / 128), 256>>>(Wo, bo, out);
}

// round 2
// speedup vs baseline: 1.1459x; 1.1459x over previous
#include <cuda_runtime.h>
#include <math.h>
#include <stdint.h>

// Problem constants
constexpr int B_  = 4;
constexpr int T_  = 2048;
constexpr int D_  = 1024;
constexpr int H_  = 16;
constexpr int DH_ = 64;
constexpr int M_  = B_ * T_;   // 8192
constexpr int N_  = D_;        // 1024
constexpr int K_  = D_;        // 1024

// Scratch (device globals: allocation-free per harness rules). 4 x 32 MB.
__device__ float g_q  [M_ * D_];
__device__ float g_k  [M_ * D_];
__device__ float g_v  [M_ * D_];
__device__ float g_ctx[M_ * D_];

// ---------------------------------------------------------------------------
// 3xTF32 tensor-core GEMM: C[M,N] = A[M,K] @ W[K,N] (+ bias)
// CTA tile 128x128, BK=16, 256 threads = 8 warps as 2(M) x 4(N),
// warp tile 64x32 -> 4x4 m16n8k8 fragments. A split A_hi+A_lo (tf32),
// C = Ah*Bh + Ah*Bl + Al*Bh  => ~fp32 accuracy on tensor pipe.
// ---------------------------------------------------------------------------
constexpr int BM  = 128;
constexpr int BN  = 128;
constexpr int BKt = 16;

#define MMA_TF32(d, a, b)                                                    \
    asm volatile(                                                            \
        "mma.sync.aligned.m16n8k8.row.col.f32.tf32.tf32.f32 "                \
        "{%0,%1,%2,%3}, {%4,%5,%6,%7}, {%8,%9}, {%0,%1,%2,%3};"              \
        : "+f"((d)[0]), "+f"((d)[1]), "+f"((d)[2]), "+f"((d)[3])             \
        : "r"((a)[0]), "r"((a)[1]), "r"((a)[2]), "r"((a)[3]),                \
          "r"((b)[0]), "r"((b)[1]))

__device__ __forceinline__ void split_tf32(float x, uint32_t& hi, uint32_t& lo) {
    uint32_t h = __float_as_uint(x) & 0xFFFFE000u;   // keep 10 mantissa bits
    hi = h;
    lo = __float_as_uint(x - __uint_as_float(h));    // exact residual
}

__device__ __forceinline__ void tgemm_body(const float* __restrict__ A,
                                           const float* __restrict__ W,
                                           float* __restrict__ C,
                                           const float* __restrict__ bias) {
    __shared__ float As[BKt][BM + 4];   // transposed: As[k][m]
    __shared__ float Bs[BKt][BN + 4];   // natural:    Bs[k][n]

    const int t    = threadIdx.x;
    const int lane = t & 31;
    const int wid  = t >> 5;
    const int wM   = wid & 1;          // 0..1 -> 64-row slab
    const int wN   = wid >> 1;         // 0..3 -> 32-col slab
    const int g    = lane >> 2;        // group id 0..7
    const int tg   = lane & 3;         // thread-in-group 0..3

    const int r0 = blockIdx.y * BM;
    const int c0 = blockIdx.x * BN;

    // Global-load indexing (2 float4 per thread per tile, each matrix)
    const int arow  = t >> 2;          // 0..63  (+64 for second)
    const int acol4 = (t & 3) * 4;     // 0,4,8,12
    const int brow  = t >> 5;          // 0..7   (+8 for second)
    const int bcol4 = (t & 31) * 4;    // 0..124

    float acc[4][4][4];
#pragma unroll
    for (int i = 0; i < 4; ++i)
#pragma unroll
        for (int j = 0; j < 4; ++j)
#pragma unroll
            for (int r = 0; r < 4; ++r) acc[i][j][r] = 0.f;

    const int NTILE = K_ / BKt;
    float4 pa0, pa1, pb0, pb1;

    // Prefetch tile 0
    {
        const size_t a0 = (size_t)(r0 + arow) * K_ + acol4;
        const size_t a1 = (size_t)(r0 + arow + 64) * K_ + acol4;
        pa0 = *reinterpret_cast<const float4*>(&A[a0]);
        pa1 = *reinterpret_cast<const float4*>(&A[a1]);
        const size_t b0 = (size_t)brow * N_ + c0 + bcol4;
        const size_t b1 = (size_t)(brow + 8) * N_ + c0 + bcol4;
        pb0 = *reinterpret_cast<const float4*>(&W[b0]);
        pb1 = *reinterpret_cast<const float4*>(&W[b1]);
    }

    for (int kt = 0; kt < NTILE; ++kt) {
        // Commit prefetched tile to smem
        As[acol4 + 0][arow]      = pa0.x;
        As[acol4 + 1][arow]      = pa0.y;
        As[acol4 + 2][arow]      = pa0.z;
        As[acol4 + 3][arow]      = pa0.w;
        As[acol4 + 0][arow + 64] = pa1.x;
        As[acol4 + 1][arow + 64] = pa1.y;
        As[acol4 + 2][arow + 64] = pa1.z;
        As[acol4 + 3][arow + 64] = pa1.w;
        *reinterpret_cast<float4*>(&Bs[brow][bcol4])     = pb0;
        *reinterpret_cast<float4*>(&Bs[brow + 8][bcol4]) = pb1;
        __syncthreads();

        // Prefetch next tile
        if (kt + 1 < NTILE) {
            const int kn = (kt + 1) * BKt;
            const size_t a0 = (size_t)(r0 + arow) * K_ + kn + acol4;
            const size_t a1 = (size_t)(r0 + arow + 64) * K_ + kn + acol4;
            pa0 = *reinterpret_cast<const float4*>(&A[a0]);
            pa1 = *reinterpret_cast<const float4*>(&A[a1]);
            const size_t b0 = (size_t)(kn + brow) * N_ + c0 + bcol4;
            const size_t b1 = (size_t)(kn + brow + 8) * N_ + c0 + bcol4;
            pb0 = *reinterpret_cast<const float4*>(&W[b0]);
            pb1 = *reinterpret_cast<const float4*>(&W[b1]);
        }

        // Compute: 2 k-steps of 8
#pragma unroll
        for (int ks = 0; ks < 2; ++ks) {
            const int k0 = ks * 8 + tg;
            uint32_t ah[4][4], al[4][4];
#pragma unroll
            for (int mf = 0; mf < 4; ++mf) {
                const int rb = wM * 64 + mf * 16 + g;
                split_tf32(As[k0][rb],         ah[mf][0], al[mf][0]);
                split_tf32(As[k0][rb + 8],     ah[mf][1], al[mf][1]);
                split_tf32(As[k0 + 4][rb],     ah[mf][2], al[mf][2]);
                split_tf32(As[k0 + 4][rb + 8], ah[mf][3], al[mf][3]);
            }
            uint32_t bh[4][2], bl[4][2];
#pragma unroll
            for (int nf = 0; nf < 4; ++nf) {
                const int cc = wN * 32 + nf * 8 + g;
                split_tf32(Bs[k0][cc],     bh[nf][0], bl[nf][0]);
                split_tf32(Bs[k0 + 4][cc], bh[nf][1], bl[nf][1]);
            }
#pragma unroll
            for (int mf = 0; mf < 4; ++mf)
#pragma unroll
                for (int nf = 0; nf < 4; ++nf) {
                    MMA_TF32(acc[mf][nf], al[mf], bh[nf]);
                    MMA_TF32(acc[mf][nf], ah[mf], bl[nf]);
                    MMA_TF32(acc[mf][nf], ah[mf], bh[nf]);
                }
        }
        __syncthreads();
    }

    // Epilogue: c0,c1 at (row, 2*tg), c2,c3 at (row+8, 2*tg)
#pragma unroll
    for (int mf = 0; mf < 4; ++mf) {
#pragma unroll
        for (int nf = 0; nf < 4; ++nf) {
            const int row = r0 + wM * 64 + mf * 16 + g;
            const int col = c0 + wN * 32 + nf * 8 + 2 * tg;
            float2 v0 = make_float2(acc[mf][nf][0], acc[mf][nf][1]);
            float2 v1 = make_float2(acc[mf][nf][2], acc[mf][nf][3]);
            if (bias) {
                const float b0v = bias[col], b1v = bias[col + 1];
                v0.x += b0v; v0.y += b1v;
                v1.x += b0v; v1.y += b1v;
            }
            *reinterpret_cast<float2*>(&C[(size_t)row * N_ + col])       = v0;
            *reinterpret_cast<float2*>(&C[(size_t)(row + 8) * N_ + col]) = v1;
        }
    }
}

__global__ __launch_bounds__(256, 1)
void tgemm_qkv(const float* __restrict__ x,
               const float* __restrict__ Wq,
               const float* __restrict__ Wk,
               const float* __restrict__ Wv) {
    const float* W = (blockIdx.z == 0) ? Wq : (blockIdx.z == 1) ? Wk : Wv;
    float* C = (blockIdx.z == 0) ? g_q : (blockIdx.z == 1) ? g_k : g_v;
    tgemm_body(x, W, C, nullptr);
}

__global__ __launch_bounds__(256, 1)
void tgemm_out(const float* __restrict__ Wo,
               const float* __restrict__ bo,
               float* __restrict__ out) {
    tgemm_body(g_ctx, Wo, out, bo);
}

// ---------------------------------------------------------------------------
// Flash attention (causal) — unchanged from R0.
// ---------------------------------------------------------------------------
constexpr int BQ  = 128;
constexpr int BKV = 64;
constexpr int QS_STRIDE = 68;

template <int CN>
__device__ __forceinline__ void attn_chunk(const float* __restrict__ Ks,
                                           const float* __restrict__ Vs,
                                           int c,
                                           const float (&q)[64],
                                           float (&o)[64],
                                           float& m, float& l) {
    float s[CN];
    float mloc = m;
#pragma unroll
    for (int jj = 0; jj < CN; ++jj) {
        const float4* kr = reinterpret_cast<const float4*>(&Ks[(c + jj) * 64]);
        float acc = 0.f;
#pragma unroll
        for (int d4 = 0; d4 < 16; ++d4) {
            float4 kv = kr[d4];
            acc += q[d4 * 4 + 0] * kv.x;
            acc += q[d4 * 4 + 1] * kv.y;
            acc += q[d4 * 4 + 2] * kv.z;
            acc += q[d4 * 4 + 3] * kv.w;
        }
        s[jj] = acc * 0.125f;
        mloc = fmaxf(mloc, s[jj]);
    }
    if (mloc > m) {
        const float alpha = __expf(m - mloc);
        l *= alpha;
#pragma unroll
        for (int d = 0; d < 64; ++d) o[d] *= alpha;
        m = mloc;
    }
#pragma unroll
    for (int jj = 0; jj < CN; ++jj) {
        const float p = __expf(s[jj] - m);
        l += p;
        const float4* vr = reinterpret_cast<const float4*>(&Vs[(c + jj) * 64]);
#pragma unroll
        for (int d4 = 0; d4 < 16; ++d4) {
            float4 vv = vr[d4];
            o[d4 * 4 + 0] += p * vv.x;
            o[d4 * 4 + 1] += p * vv.y;
            o[d4 * 4 + 2] += p * vv.z;
            o[d4 * 4 + 3] += p * vv.w;
        }
    }
}

__global__ __launch_bounds__(128, 3)
void flash_attn() {
    extern __shared__ float sm[];
    float* Qs = sm;
    float* Ks = sm + BQ * QS_STRIDE;
    float* Vs = Ks + BKV * 64;

    const int t  = threadIdx.x;
    const int h  = blockIdx.y;
    const int b  = blockIdx.z;
    const int q0 = blockIdx.x * BQ;
    const size_t base = (size_t)b * T_ * D_ + (size_t)h * DH_;

    for (int idx = t; idx < BQ * 16; idx += 128) {
        const int r = idx >> 4, c4 = (idx & 15) * 4;
        *reinterpret_cast<float4*>(&Qs[r * QS_STRIDE + c4]) =
            *reinterpret_cast<const float4*>(&g_q[base + (size_t)(q0 + r) * D_ + c4]);
    }
    __syncthreads();

    float q[64];
#pragma unroll
    for (int d4 = 0; d4 < 16; ++d4) {
        float4 v = *reinterpret_cast<const float4*>(&Qs[t * QS_STRIDE + d4 * 4]);
        q[d4 * 4 + 0] = v.x; q[d4 * 4 + 1] = v.y;
        q[d4 * 4 + 2] = v.z; q[d4 * 4 + 3] = v.w;
    }

    float o[64];
#pragma unroll
    for (int d = 0; d < 64; ++d) o[d] = 0.f;
    float m = -1e30f, l = 0.f;

    const int tq     = q0 + t;
    const int ntiles = (q0 + BQ) / BKV;

    for (int j = 0; j < ntiles; ++j) {
        for (int idx = t; idx < BKV * 16; idx += 128) {
            const int r = idx >> 4, c4 = (idx & 15) * 4;
            const size_t gidx = base + (size_t)(j * BKV + r) * D_ + c4;
            *reinterpret_cast<float4*>(&Ks[r * 64 + c4]) =
                *reinterpret_cast<const float4*>(&g_k[gidx]);
            *reinterpret_cast<float4*>(&Vs[r * 64 + c4]) =
                *reinterpret_cast<const float4*>(&g_v[gidx]);
        }
        __syncthreads();

        int valid = tq - j * BKV + 1;
        if (valid > BKV) valid = BKV;
        if (valid == BKV) {
#pragma unroll
            for (int c = 0; c < BKV; c += 16)
                attn_chunk<16>(Ks, Vs, c, q, o, m, l);
        } else if (valid > 0) {
            for (int c = 0; c < valid; ++c)
                attn_chunk<1>(Ks, Vs, c, q, o, m, l);
        }
        __syncthreads();
    }

    const float inv = 1.f / l;
#pragma unroll
    for (int d4 = 0; d4 < 16; ++d4) {
        float4 v;
        v.x = o[d4 * 4 + 0] * inv; v.y = o[d4 * 4 + 1] * inv;
        v.z = o[d4 * 4 + 2] * inv; v.w = o[d4 * 4 + 3] * inv;
        *reinterpret_cast<float4*>(&Qs[t * QS_STRIDE + d4 * 4]) = v;
    }
    __syncthreads();
    for (int idx = t; idx < BQ * 16; idx += 128) {
        const int r = idx >> 4, c4 = (idx & 15) * 4;
        *reinterpret_cast<float4*>(&g_ctx[base + (size_t)(q0 + r) * D_ + c4]) =
            *reinterpret_cast<const float4*>(&Qs[r * QS_STRIDE + c4]);
    }
}

// ---------------------------------------------------------------------------
extern "C" void kernel_launch(void* const* d_in, const int* in_sizes, int n_in,
                              void* d_out, int out_size) {
    const float* x  = (const float*)d_in[0];
    const float* Wq = (const float*)d_in[1];
    const float* Wk = (const float*)d_in[2];
    const float* Wv = (const float*)d_in[3];
    const float* Wo = (const float*)d_in[4];
    const float* bo = (const float*)d_in[5];
    float* out = (float*)d_out;

    // 1) QKV projections on tensor cores (3xTF32)
    dim3 gq(N_ / BN, M_ / BM, 3);
    tgemm_qkv<<<gq, 256>>>(x, Wq, Wk, Wv);

    // 2) Causal flash attention
    const size_t smem = (size_t)(BQ * QS_STRIDE + 2 * BKV * 64) * sizeof(float);
    cudaFuncSetAttribute(flash_attn,
                         cudaFuncAttributeMaxDynamicSharedMemorySize, (int)smem);
    flash_attn<<<dim3(T_ / BQ, H_, B_), 128, smem>>>();

    // 3) Output projection (+bias) on tensor cores
    tgemm_out<<<dim3(N_ / BN, M_ / BM), 256>>>(Wo, bo, out);
}

// round 3
// speedup vs baseline: 2.6708x; 2.3308x over previous
#include <cuda_runtime.h>
#include <math.h>
#include <stdint.h>

// Problem constants
constexpr int B_  = 4;
constexpr int T_  = 2048;
constexpr int D_  = 1024;
constexpr int H_  = 16;
constexpr int DH_ = 64;
constexpr int M_  = B_ * T_;   // 8192
constexpr int N_  = D_;        // 1024
constexpr int K_  = D_;        // 1024

// Scratch (device globals: allocation-free per harness rules).
__device__ float g_q  [M_ * D_];
__device__ float g_k  [M_ * D_];
__device__ float g_v  [M_ * D_];
__device__ float g_vT [M_ * D_];   // [B][D][T] transposed V
__device__ float g_ctx[M_ * D_];

// ---------------------------------------------------------------------------
// Common tensor-core helpers (m16n8k8 tf32) — layouts verified in R1.
// ---------------------------------------------------------------------------
#define MMA_TF32(d, a, b)                                                    \
    asm volatile(                                                            \
        "mma.sync.aligned.m16n8k8.row.col.f32.tf32.tf32.f32 "                \
        "{%0,%1,%2,%3}, {%4,%5,%6,%7}, {%8,%9}, {%0,%1,%2,%3};"              \
        : "+f"((d)[0]), "+f"((d)[1]), "+f"((d)[2]), "+f"((d)[3])             \
        : "r"((a)[0]), "r"((a)[1]), "r"((a)[2]), "r"((a)[3]),                \
          "r"((b)[0]), "r"((b)[1]))

__device__ __forceinline__ void split_tf32(float x, uint32_t& hi, uint32_t& lo) {
    uint32_t h = __float_as_uint(x) & 0xFFFFE000u;
    hi = h;
    lo = __float_as_uint(x - __uint_as_float(h));
}

__device__ __forceinline__ float rna_tf32(float x) {
    uint32_t u = __float_as_uint(x);
    u = (u + 0x1000u) & 0xFFFFE000u;   // round-to-nearest to tf32
    return __uint_as_float(u);
}

// ---------------------------------------------------------------------------
// 3xTF32 GEMM (unchanged from R1): C[M,N] = A[M,K] @ W[K,N] (+ bias)
// ---------------------------------------------------------------------------
constexpr int BM  = 128;
constexpr int BN  = 128;
constexpr int BKt = 16;

__device__ __forceinline__ void tgemm_body(const float* __restrict__ A,
                                           const float* __restrict__ W,
                                           float* __restrict__ C,
                                           const float* __restrict__ bias) {
    __shared__ float As[BKt][BM + 4];
    __shared__ float Bs[BKt][BN + 4];

    const int t    = threadIdx.x;
    const int lane = t & 31;
    const int wid  = t >> 5;
    const int wM   = wid & 1;
    const int wN   = wid >> 1;
    const int g    = lane >> 2;
    const int tg   = lane & 3;

    const int r0 = blockIdx.y * BM;
    const int c0 = blockIdx.x * BN;

    const int arow  = t >> 2;
    const int acol4 = (t & 3) * 4;
    const int brow  = t >> 5;
    const int bcol4 = (t & 31) * 4;

    float acc[4][4][4];
#pragma unroll
    for (int i = 0; i < 4; ++i)
#pragma unroll
        for (int j = 0; j < 4; ++j)
#pragma unroll
            for (int r = 0; r < 4; ++r) acc[i][j][r] = 0.f;

    const int NTILE = K_ / BKt;
    float4 pa0, pa1, pb0, pb1;
    {
        pa0 = *reinterpret_cast<const float4*>(&A[(size_t)(r0 + arow) * K_ + acol4]);
        pa1 = *reinterpret_cast<const float4*>(&A[(size_t)(r0 + arow + 64) * K_ + acol4]);
        pb0 = *reinterpret_cast<const float4*>(&W[(size_t)brow * N_ + c0 + bcol4]);
        pb1 = *reinterpret_cast<const float4*>(&W[(size_t)(brow + 8) * N_ + c0 + bcol4]);
    }

    for (int kt = 0; kt < NTILE; ++kt) {
        As[acol4 + 0][arow]      = pa0.x;
        As[acol4 + 1][arow]      = pa0.y;
        As[acol4 + 2][arow]      = pa0.z;
        As[acol4 + 3][arow]      = pa0.w;
        As[acol4 + 0][arow + 64] = pa1.x;
        As[acol4 + 1][arow + 64] = pa1.y;
        As[acol4 + 2][arow + 64] = pa1.z;
        As[acol4 + 3][arow + 64] = pa1.w;
        *reinterpret_cast<float4*>(&Bs[brow][bcol4])     = pb0;
        *reinterpret_cast<float4*>(&Bs[brow + 8][bcol4]) = pb1;
        __syncthreads();

        if (kt + 1 < NTILE) {
            const int kn = (kt + 1) * BKt;
            pa0 = *reinterpret_cast<const float4*>(&A[(size_t)(r0 + arow) * K_ + kn + acol4]);
            pa1 = *reinterpret_cast<const float4*>(&A[(size_t)(r0 + arow + 64) * K_ + kn + acol4]);
            pb0 = *reinterpret_cast<const float4*>(&W[(size_t)(kn + brow) * N_ + c0 + bcol4]);
            pb1 = *reinterpret_cast<const float4*>(&W[(size_t)(kn + brow + 8) * N_ + c0 + bcol4]);
        }

#pragma unroll
        for (int ks = 0; ks < 2; ++ks) {
            const int k0 = ks * 8 + tg;
            uint32_t ah[4][4], al[4][4];
#pragma unroll
            for (int mf = 0; mf < 4; ++mf) {
                const int rb = wM * 64 + mf * 16 + g;
                split_tf32(As[k0][rb],         ah[mf][0], al[mf][0]);
                split_tf32(As[k0][rb + 8],     ah[mf][1], al[mf][1]);
                split_tf32(As[k0 + 4][rb],     ah[mf][2], al[mf][2]);
                split_tf32(As[k0 + 4][rb + 8], ah[mf][3], al[mf][3]);
            }
            uint32_t bh[4][2], bl[4][2];
#pragma unroll
            for (int nf = 0; nf < 4; ++nf) {
                const int cc = wN * 32 + nf * 8 + g;
                split_tf32(Bs[k0][cc],     bh[nf][0], bl[nf][0]);
                split_tf32(Bs[k0 + 4][cc], bh[nf][1], bl[nf][1]);
            }
#pragma unroll
            for (int mf = 0; mf < 4; ++mf)
#pragma unroll
                for (int nf = 0; nf < 4; ++nf) {
                    MMA_TF32(acc[mf][nf], al[mf], bh[nf]);
                    MMA_TF32(acc[mf][nf], ah[mf], bl[nf]);
                    MMA_TF32(acc[mf][nf], ah[mf], bh[nf]);
                }
        }
        __syncthreads();
    }

#pragma unroll
    for (int mf = 0; mf < 4; ++mf) {
#pragma unroll
        for (int nf = 0; nf < 4; ++nf) {
            const int row = r0 + wM * 64 + mf * 16 + g;
            const int col = c0 + wN * 32 + nf * 8 + 2 * tg;
            float2 v0 = make_float2(acc[mf][nf][0], acc[mf][nf][1]);
            float2 v1 = make_float2(acc[mf][nf][2], acc[mf][nf][3]);
            if (bias) {
                const float b0v = bias[col], b1v = bias[col + 1];
                v0.x += b0v; v0.y += b1v;
                v1.x += b0v; v1.y += b1v;
            }
            *reinterpret_cast<float2*>(&C[(size_t)row * N_ + col])       = v0;
            *reinterpret_cast<float2*>(&C[(size_t)(row + 8) * N_ + col]) = v1;
        }
    }
}

__global__ __launch_bounds__(256, 1)
void tgemm_qkv(const float* __restrict__ x,
               const float* __restrict__ Wq,
               const float* __restrict__ Wk,
               const float* __restrict__ Wv) {
    const float* W = (blockIdx.z == 0) ? Wq : (blockIdx.z == 1) ? Wk : Wv;
    float* C = (blockIdx.z == 0) ? g_q : (blockIdx.z == 1) ? g_k : g_v;
    tgemm_body(x, W, C, nullptr);
}

__global__ __launch_bounds__(256, 1)
void tgemm_out(const float* __restrict__ Wo,
               const float* __restrict__ bo,
               float* __restrict__ out) {
    tgemm_body(g_ctx, Wo, out, bo);
}

// ---------------------------------------------------------------------------
// V transpose: g_vT[b][d][t] = rna_tf32(g_v[b][t][d]).  Tiled 32x32.
// ---------------------------------------------------------------------------
__global__ __launch_bounds__(256)
void transpose_v() {
    __shared__ float tile[32][33];
    const int b  = blockIdx.z;
    const int t0 = blockIdx.x * 32;
    const int d0 = blockIdx.y * 32;
    const int tx = threadIdx.x;
    const int ty = threadIdx.y;   // block (32, 8)
#pragma unroll
    for (int i = 0; i < 32; i += 8)
        tile[ty + i][tx] = g_v[(size_t)b * T_ * D_ + (size_t)(t0 + ty + i) * D_ + d0 + tx];
    __syncthreads();
#pragma unroll
    for (int i = 0; i < 32; i += 8)
        g_vT[(size_t)b * D_ * T_ + (size_t)(d0 + ty + i) * T_ + t0 + tx] =
            rna_tf32(tile[tx][ty + i]);
}

// ---------------------------------------------------------------------------
// Tensor-core causal flash attention.
// CTA: 128 threads (4 warps), 64 q-rows (16/warp), KV tiles of 64.
// QK^T: 3xTF32 (Q frags pre-scaled & split in regs, K split on the fly).
// PV:   plain tf32 (P RNA-rounded via warp-private smem, V^T from g_vT).
// ---------------------------------------------------------------------------
constexpr int FSTR = 68;   // padded smem row stride (floats)

__global__ __launch_bounds__(128)
void flash_attn_tc() {
    extern __shared__ float sm[];
    float* Qs = sm;                    // 64 x FSTR ; reused as Ps
    float* Ks = sm + 64 * FSTR;        // 64 x FSTR : K[kv][d]
    float* Vt = sm + 2 * 64 * FSTR;    // 64 x FSTR : V^T[d][kv]

    const int t    = threadIdx.x;
    const int lane = t & 31;
    const int w    = t >> 5;
    const int g    = lane >> 2;
    const int tg   = lane & 3;

    const int qb = (int)gridDim.x - 1 - (int)blockIdx.x;  // long blocks first
    const int h  = blockIdx.y;
    const int b  = blockIdx.z;
    const int q0 = qb * 64;
    const size_t qkb = (size_t)b * T_ * D_ + (size_t)h * DH_;
    const size_t vtb = (size_t)b * D_ * T_ + (size_t)h * DH_ * T_;

    // Load Q tile (pre-scaled by 1/sqrt(64))
    for (int idx = t; idx < 64 * 16; idx += 128) {
        const int r = idx >> 4, c4 = (idx & 15) * 4;
        float4 v = *reinterpret_cast<const float4*>(
            &g_q[qkb + (size_t)(q0 + r) * D_ + c4]);
        v.x *= 0.125f; v.y *= 0.125f; v.z *= 0.125f; v.w *= 0.125f;
        *reinterpret_cast<float4*>(&Qs[r * FSTR + c4]) = v;
    }
    __syncthreads();

    // Q fragments (hi/lo split) in registers
    const int r0 = w * 16 + g;
    const int r1 = r0 + 8;
    uint32_t qh[8][4], ql[8][4];
#pragma unroll
    for (int k = 0; k < 8; ++k) {
        split_tf32(Qs[r0 * FSTR + k * 8 + tg],     qh[k][0], ql[k][0]);
        split_tf32(Qs[r1 * FSTR + k * 8 + tg],     qh[k][1], ql[k][1]);
        split_tf32(Qs[r0 * FSTR + k * 8 + tg + 4], qh[k][2], ql[k][2]);
        split_tf32(Qs[r1 * FSTR + k * 8 + tg + 4], qh[k][3], ql[k][3]);
    }

    float o[8][4];
#pragma unroll
    for (int nf = 0; nf < 8; ++nf)
#pragma unroll
        for (int r = 0; r < 4; ++r) o[nf][r] = 0.f;
    float m0 = -1e30f, m1 = -1e30f, l0 = 0.f, l1 = 0.f;

    const int ntiles = qb + 1;
    for (int kt = 0; kt < ntiles; ++kt) {
        // Load K tile [kv][d] and V^T tile [d][kv] (both coalesced)
        for (int idx = t; idx < 64 * 16; idx += 128) {
            const int r = idx >> 4, c4 = (idx & 15) * 4;
            *reinterpret_cast<float4*>(&Ks[r * FSTR + c4]) =
                *reinterpret_cast<const float4*>(
                    &g_k[qkb + (size_t)(kt * 64 + r) * D_ + c4]);
            *reinterpret_cast<float4*>(&Vt[r * FSTR + c4]) =
                *reinterpret_cast<const float4*>(
                    &g_vT[vtb + (size_t)r * T_ + kt * 64 + c4]);
        }
        __syncthreads();   // also guards Qs->Ps reuse on first iter

        // S = Q K^T (3xTF32)
        float s[8][4];
#pragma unroll
        for (int nf = 0; nf < 8; ++nf)
#pragma unroll
            for (int r = 0; r < 4; ++r) s[nf][r] = 0.f;

#pragma unroll
        for (int k = 0; k < 8; ++k) {
#pragma unroll
            for (int nf = 0; nf < 8; ++nf) {
                const float kv0 = Ks[(nf * 8 + g) * FSTR + k * 8 + tg];
                const float kv1 = Ks[(nf * 8 + g) * FSTR + k * 8 + tg + 4];
                uint32_t kh[2], kl[2];
                split_tf32(kv0, kh[0], kl[0]);
                split_tf32(kv1, kh[1], kl[1]);
                MMA_TF32(s[nf], ql[k], kh);
                MMA_TF32(s[nf], qh[k], kl);
                MMA_TF32(s[nf], qh[k], kh);
            }
        }

        // Causal mask (diagonal tile only; local coords valid since kb0==q0)
        if (kt == qb) {
#pragma unroll
            for (int nf = 0; nf < 8; ++nf) {
                const int c = nf * 8 + 2 * tg;
                if (c     > r0) s[nf][0] = -1e30f;
                if (c + 1 > r0) s[nf][1] = -1e30f;
                if (c     > r1) s[nf][2] = -1e30f;
                if (c + 1 > r1) s[nf][3] = -1e30f;
            }
        }

        // Online softmax (rows r0 / r1)
        float mx0 = -1e30f, mx1 = -1e30f;
#pragma unroll
        for (int nf = 0; nf < 8; ++nf) {
            mx0 = fmaxf(mx0, fmaxf(s[nf][0], s[nf][1]));
            mx1 = fmaxf(mx1, fmaxf(s[nf][2], s[nf][3]));
        }
        mx0 = fmaxf(mx0, __shfl_xor_sync(0xffffffffu, mx0, 1));
        mx0 = fmaxf(mx0, __shfl_xor_sync(0xffffffffu, mx0, 2));
        mx1 = fmaxf(mx1, __shfl_xor_sync(0xffffffffu, mx1, 1));
        mx1 = fmaxf(mx1, __shfl_xor_sync(0xffffffffu, mx1, 2));
        const float mn0 = fmaxf(m0, mx0);
        const float mn1 = fmaxf(m1, mx1);
        const float a0 = __expf(m0 - mn0);
        const float a1 = __expf(m1 - mn1);

        float rs0 = 0.f, rs1 = 0.f;
#pragma unroll
        for (int nf = 0; nf < 8; ++nf) {
            s[nf][0] = __expf(s[nf][0] - mn0); rs0 += s[nf][0];
            s[nf][1] = __expf(s[nf][1] - mn0); rs0 += s[nf][1];
            s[nf][2] = __expf(s[nf][2] - mn1); rs1 += s[nf][2];
            s[nf][3] = __expf(s[nf][3] - mn1); rs1 += s[nf][3];
            o[nf][0] *= a0; o[nf][1] *= a0;
            o[nf][2] *= a1; o[nf][3] *= a1;
        }
        rs0 += __shfl_xor_sync(0xffffffffu, rs0, 1);
        rs0 += __shfl_xor_sync(0xffffffffu, rs0, 2);
        rs1 += __shfl_xor_sync(0xffffffffu, rs1, 1);
        rs1 += __shfl_xor_sync(0xffffffffu, rs1, 2);
        l0 = l0 * a0 + rs0;
        l1 = l1 * a1 + rs1;
        m0 = mn0; m1 = mn1;

        // Stage P (RNA tf32) in warp-private smem rows (C-layout -> A-layout)
        float* Ps = Qs;
#pragma unroll
        for (int nf = 0; nf < 8; ++nf) {
            const int c = nf * 8 + 2 * tg;
            Ps[r0 * FSTR + c]     = rna_tf32(s[nf][0]);
            Ps[r0 * FSTR + c + 1] = rna_tf32(s[nf][1]);
            Ps[r1 * FSTR + c]     = rna_tf32(s[nf][2]);
            Ps[r1 * FSTR + c + 1] = rna_tf32(s[nf][3]);
        }
        // no barrier needed: each warp reads only its own 16 rows

        // O += P V  (plain tf32)
#pragma unroll
        for (int k = 0; k < 8; ++k) {
            uint32_t pa[4];
            pa[0] = __float_as_uint(Ps[r0 * FSTR + k * 8 + tg]);
            pa[1] = __float_as_uint(Ps[r1 * FSTR + k * 8 + tg]);
            pa[2] = __float_as_uint(Ps[r0 * FSTR + k * 8 + tg + 4]);
            pa[3] = __float_as_uint(Ps[r1 * FSTR + k * 8 + tg + 4]);
#pragma unroll
            for (int nf = 0; nf < 8; ++nf) {
                uint32_t vb[2];
                vb[0] = __float_as_uint(Vt[(nf * 8 + g) * FSTR + k * 8 + tg]);
                vb[1] = __float_as_uint(Vt[(nf * 8 + g) * FSTR + k * 8 + tg + 4]);
                MMA_TF32(o[nf], pa, vb);
            }
        }
        __syncthreads();   // before next tile overwrites Ks/Vt
    }

    // Normalize and store ctx
    const float i0 = 1.f / l0;
    const float i1 = 1.f / l1;
#pragma unroll
    for (int nf = 0; nf < 8; ++nf) {
        const int c = nf * 8 + 2 * tg;
        float2 v0 = make_float2(o[nf][0] * i0, o[nf][1] * i0);
        float2 v1 = make_float2(o[nf][2] * i1, o[nf][3] * i1);
        *reinterpret_cast<float2*>(&g_ctx[qkb + (size_t)(q0 + r0) * D_ + c]) = v0;
        *reinterpret_cast<float2*>(&g_ctx[qkb + (size_t)(q0 + r1) * D_ + c]) = v1;
    }
}

// ---------------------------------------------------------------------------
extern "C" void kernel_launch(void* const* d_in, const int* in_sizes, int n_in,
                              void* d_out, int out_size) {
    const float* x  = (const float*)d_in[0];
    const float* Wq = (const float*)d_in[1];
    const float* Wk = (const float*)d_in[2];
    const float* Wv = (const float*)d_in[3];
    const float* Wo = (const float*)d_in[4];
    const float* bo = (const float*)d_in[5];
    float* out = (float*)d_out;

    // 1) QKV projections (3xTF32 tensor cores)
    tgemm_qkv<<<dim3(N_ / BN, M_ / BM, 3), 256>>>(x, Wq, Wk, Wv);

    // 2) V transpose (+RNA tf32 rounding)
    transpose_v<<<dim3(T_ / 32, D_ / 32, B_), dim3(32, 8)>>>();

    // 3) Tensor-core causal flash attention
    const int smem = 3 * 64 * FSTR * sizeof(float);  // 52,224 B
    cudaFuncSetAttribute(flash_attn_tc,
                         cudaFuncAttributeMaxDynamicSharedMemorySize, smem);
    flash_attn_tc<<<dim3(T_ / 64, H_, B_), 128, smem>>>();

    // 4) Output projection (+bias)
    tgemm_out<<<dim3(N_ / BN, M_ / BM), 256>>>(Wo, bo, out);
}

// round 4
// speedup vs baseline: 3.1466x; 1.1782x over previous
#include <cuda_runtime.h>
#include <cuda_bf16.h>
#include <math.h>
#include <stdint.h>

// Problem constants
constexpr int B_  = 4;
constexpr int T_  = 2048;
constexpr int D_  = 1024;
constexpr int H_  = 16;
constexpr int DH_ = 64;
constexpr int M_  = B_ * T_;   // 8192
constexpr int N_  = D_;        // 1024
constexpr int K_  = D_;        // 1024

// Scratch (device globals: allocation-free per harness rules).
__device__ float g_q  [M_ * D_];
__device__ float g_k  [M_ * D_];
__device__ float g_v  [M_ * D_];
__device__ float g_vT [M_ * D_];   // [B][D][T] transposed V
__device__ float g_ctx[M_ * D_];

// ---------------------------------------------------------------------------
// Tensor-core helpers
// ---------------------------------------------------------------------------
#define MMA_TF32(d, a, b)                                                    \
    asm volatile(                                                            \
        "mma.sync.aligned.m16n8k8.row.col.f32.tf32.tf32.f32 "                \
        "{%0,%1,%2,%3}, {%4,%5,%6,%7}, {%8,%9}, {%0,%1,%2,%3};"              \
        : "+f"((d)[0]), "+f"((d)[1]), "+f"((d)[2]), "+f"((d)[3])             \
        : "r"((a)[0]), "r"((a)[1]), "r"((a)[2]), "r"((a)[3]),                \
          "r"((b)[0]), "r"((b)[1]))

#define MMA_BF16(d, a, b)                                                    \
    asm volatile(                                                            \
        "mma.sync.aligned.m16n8k16.row.col.f32.bf16.bf16.f32 "               \
        "{%0,%1,%2,%3}, {%4,%5,%6,%7}, {%8,%9}, {%0,%1,%2,%3};"              \
        : "+f"((d)[0]), "+f"((d)[1]), "+f"((d)[2]), "+f"((d)[3])             \
        : "r"((a)[0]), "r"((a)[1]), "r"((a)[2]), "r"((a)[3]),                \
          "r"((b)[0]), "r"((b)[1]))

__device__ __forceinline__ void split_tf32(float x, uint32_t& hi, uint32_t& lo) {
    uint32_t h = __float_as_uint(x) & 0xFFFFE000u;
    hi = h;
    lo = __float_as_uint(x - __uint_as_float(h));
}

__device__ __forceinline__ float rna_tf32(float x) {
    uint32_t u = __float_as_uint(x);
    u = (u + 0x1000u) & 0xFFFFE000u;
    return __uint_as_float(u);
}

// Split (a,b) into bf16 hi pair + bf16 lo-residual pair, packed as bf16x2.
__device__ __forceinline__ void packpair_bf16(float a, float b,
                                              uint32_t& h, uint32_t& l) {
    const float ha = __bfloat162float(__float2bfloat16(a));
    const float hb = __bfloat162float(__float2bfloat16(b));
    __nv_bfloat162 H = __floats2bfloat162_rn(ha, hb);
    __nv_bfloat162 L = __floats2bfloat162_rn(a - ha, b - hb);
    h = *reinterpret_cast<uint32_t*>(&H);
    l = *reinterpret_cast<uint32_t*>(&L);
}

// ---------------------------------------------------------------------------
// 3xBF16 GEMM: C[M,N] = A[M,K] @ W[K,N] (+ bias)
// CTA 128x128, BK=16, 8 warps (2M x 4N), warp tile 64x32 -> 4x4 m16n8k16.
// Operands split hi/lo ONCE at staging; smem holds packed bf16x2 along k.
// C = Ah*Bh + Ah*Bl + Al*Bh (fp32 accum) => ~2^-17 relative error.
// ---------------------------------------------------------------------------
constexpr int BM   = 128;
constexpr int BN   = 128;
constexpr int SSTR = 136;   // smem row stride (uint32) -> conflict-free frags

__device__ __forceinline__ void tgemm_body(const float* __restrict__ A,
                                           const float* __restrict__ W,
                                           float* __restrict__ C,
                                           const float* __restrict__ bias) {
    // [k/2][m or n] packed bf16x2 (k-even in low half)
    __shared__ uint32_t As_hi[8][SSTR], As_lo[8][SSTR];
    __shared__ uint32_t Bs_hi[8][SSTR], Bs_lo[8][SSTR];

    const int t    = threadIdx.x;
    const int lane = t & 31;
    const int wid  = t >> 5;
    const int wM   = wid & 1;
    const int wN   = wid >> 1;
    const int g    = lane >> 2;
    const int tg   = lane & 3;

    const int r0 = blockIdx.y * BM;
    const int c0 = blockIdx.x * BN;

    // A global-load indexing: float4 along k, rows arow / arow+64
    const int arow  = t >> 2;            // 0..63
    const int acol4 = (t & 3) * 4;       // 0,4,8,12
    const int akk   = (t & 3) * 2;       // k-pair index: 0,2,4,6

    // B global-load indexing: float2 pairs from adjacent k-rows
    const int bkk  = t >> 6;             // 0..3 (unit0), +4 for unit1
    const int bcol = (t & 63) * 2;       // 0..126

    float acc[4][4][4];
#pragma unroll
    for (int i = 0; i < 4; ++i)
#pragma unroll
        for (int j = 0; j < 4; ++j)
#pragma unroll
            for (int r = 0; r < 4; ++r) acc[i][j][r] = 0.f;

    const int NTILE = K_ / 16;

    float4 pa0, pa1;
    float2 pbe0, pbo0, pbe1, pbo1;
    {
        pa0 = *reinterpret_cast<const float4*>(&A[(size_t)(r0 + arow) * K_ + acol4]);
        pa1 = *reinterpret_cast<const float4*>(&A[(size_t)(r0 + arow + 64) * K_ + acol4]);
        pbe0 = *reinterpret_cast<const float2*>(&W[(size_t)(2 * bkk)     * N_ + c0 + bcol]);
        pbo0 = *reinterpret_cast<const float2*>(&W[(size_t)(2 * bkk + 1) * N_ + c0 + bcol]);
        pbe1 = *reinterpret_cast<const float2*>(&W[(size_t)(2 * bkk + 8) * N_ + c0 + bcol]);
        pbo1 = *reinterpret_cast<const float2*>(&W[(size_t)(2 * bkk + 9) * N_ + c0 + bcol]);
    }

    for (int kt = 0; kt < NTILE; ++kt) {
        // Commit prefetched tile: split + pack -> smem
        packpair_bf16(pa0.x, pa0.y, As_hi[akk][arow],          As_lo[akk][arow]);
        packpair_bf16(pa0.z, pa0.w, As_hi[akk + 1][arow],      As_lo[akk + 1][arow]);
        packpair_bf16(pa1.x, pa1.y, As_hi[akk][arow + 64],     As_lo[akk][arow + 64]);
        packpair_bf16(pa1.z, pa1.w, As_hi[akk + 1][arow + 64], As_lo[akk + 1][arow + 64]);

        packpair_bf16(pbe0.x, pbo0.x, Bs_hi[bkk][bcol],         Bs_lo[bkk][bcol]);
        packpair_bf16(pbe0.y, pbo0.y, Bs_hi[bkk][bcol + 1],     Bs_lo[bkk][bcol + 1]);
        packpair_bf16(pbe1.x, pbo1.x, Bs_hi[bkk + 4][bcol],     Bs_lo[bkk + 4][bcol]);
        packpair_bf16(pbe1.y, pbo1.y, Bs_hi[bkk + 4][bcol + 1], Bs_lo[bkk + 4][bcol + 1]);
        __syncthreads();

        // Prefetch next tile
        if (kt + 1 < NTILE) {
            const int kn = (kt + 1) * 16;
            pa0 = *reinterpret_cast<const float4*>(&A[(size_t)(r0 + arow) * K_ + kn + acol4]);
            pa1 = *reinterpret_cast<const float4*>(&A[(size_t)(r0 + arow + 64) * K_ + kn + acol4]);
            pbe0 = *reinterpret_cast<const float2*>(&W[(size_t)(kn + 2 * bkk)     * N_ + c0 + bcol]);
            pbo0 = *reinterpret_cast<const float2*>(&W[(size_t)(kn + 2 * bkk + 1) * N_ + c0 + bcol]);
            pbe1 = *reinterpret_cast<const float2*>(&W[(size_t)(kn + 2 * bkk + 8) * N_ + c0 + bcol]);
            pbo1 = *reinterpret_cast<const float2*>(&W[(size_t)(kn + 2 * bkk + 9) * N_ + c0 + bcol]);
        }

        // One k16 step: load B frags, then per-mf A frags + 12 MMAs
        uint32_t bh[4][2], bl[4][2];
#pragma unroll
        for (int nf = 0; nf < 4; ++nf) {
            const int cc = wN * 32 + nf * 8 + g;
            bh[nf][0] = Bs_hi[tg][cc];
            bh[nf][1] = Bs_hi[tg + 4][cc];
            bl[nf][0] = Bs_lo[tg][cc];
            bl[nf][1] = Bs_lo[tg + 4][cc];
        }
#pragma unroll
        for (int mf = 0; mf < 4; ++mf) {
            const int rb = wM * 64 + mf * 16 + g;
            uint32_t ah[4], al[4];
            ah[0] = As_hi[tg][rb];
            ah[1] = As_hi[tg][rb + 8];
            ah[2] = As_hi[tg + 4][rb];
            ah[3] = As_hi[tg + 4][rb + 8];
            al[0] = As_lo[tg][rb];
            al[1] = As_lo[tg][rb + 8];
            al[2] = As_lo[tg + 4][rb];
            al[3] = As_lo[tg + 4][rb + 8];
#pragma unroll
            for (int nf = 0; nf < 4; ++nf) {
                MMA_BF16(acc[mf][nf], al, bh[nf]);
                MMA_BF16(acc[mf][nf], ah, bl[nf]);
                MMA_BF16(acc[mf][nf], ah, bh[nf]);
            }
        }
        __syncthreads();
    }

    // Epilogue (C layout identical to m16n8k8 case)
#pragma unroll
    for (int mf = 0; mf < 4; ++mf) {
#pragma unroll
        for (int nf = 0; nf < 4; ++nf) {
            const int row = r0 + wM * 64 + mf * 16 + g;
            const int col = c0 + wN * 32 + nf * 8 + 2 * tg;
            float2 v0 = make_float2(acc[mf][nf][0], acc[mf][nf][1]);
            float2 v1 = make_float2(acc[mf][nf][2], acc[mf][nf][3]);
            if (bias) {
                const float b0v = bias[col], b1v = bias[col + 1];
                v0.x += b0v; v0.y += b1v;
                v1.x += b0v; v1.y += b1v;
            }
            *reinterpret_cast<float2*>(&C[(size_t)row * N_ + col])       = v0;
            *reinterpret_cast<float2*>(&C[(size_t)(row + 8) * N_ + col]) = v1;
        }
    }
}

__global__ __launch_bounds__(256, 1)
void tgemm_qkv(const float* __restrict__ x,
               const float* __restrict__ Wq,
               const float* __restrict__ Wk,
               const float* __restrict__ Wv) {
    const float* W = (blockIdx.z == 0) ? Wq : (blockIdx.z == 1) ? Wk : Wv;
    float* C = (blockIdx.z == 0) ? g_q : (blockIdx.z == 1) ? g_k : g_v;
    tgemm_body(x, W, C, nullptr);
}

__global__ __launch_bounds__(256, 1)
void tgemm_out(const float* __restrict__ Wo,
               const float* __restrict__ bo,
               float* __restrict__ out) {
    tgemm_body(g_ctx, Wo, out, bo);
}

// ---------------------------------------------------------------------------
// V transpose: g_vT[b][d][t] = rna_tf32(g_v[b][t][d]).  Tiled 32x32.
// ---------------------------------------------------------------------------
__global__ __launch_bounds__(256)
void transpose_v() {
    __shared__ float tile[32][33];
    const int b  = blockIdx.z;
    const int t0 = blockIdx.x * 32;
    const int d0 = blockIdx.y * 32;
    const int tx = threadIdx.x;
    const int ty = threadIdx.y;
#pragma unroll
    for (int i = 0; i < 32; i += 8)
        tile[ty + i][tx] = g_v[(size_t)b * T_ * D_ + (size_t)(t0 + ty + i) * D_ + d0 + tx];
    __syncthreads();
#pragma unroll
    for (int i = 0; i < 32; i += 8)
        g_vT[(size_t)b * D_ * T_ + (size_t)(d0 + ty + i) * T_ + t0 + tx] =
            rna_tf32(tile[tx][ty + i]);
}

// ---------------------------------------------------------------------------
// Tensor-core causal flash attention (unchanged from R2).
// ---------------------------------------------------------------------------
constexpr int FSTR = 68;

__global__ __launch_bounds__(128)
void flash_attn_tc() {
    extern __shared__ float sm[];
    float* Qs = sm;
    float* Ks = sm + 64 * FSTR;
    float* Vt = sm + 2 * 64 * FSTR;

    const int t    = threadIdx.x;
    const int lane = t & 31;
    const int w    = t >> 5;
    const int g    = lane >> 2;
    const int tg   = lane & 3;

    const int qb = (int)gridDim.x - 1 - (int)blockIdx.x;
    const int h  = blockIdx.y;
    const int b  = blockIdx.z;
    const int q0 = qb * 64;
    const size_t qkb = (size_t)b * T_ * D_ + (size_t)h * DH_;
    const size_t vtb = (size_t)b * D_ * T_ + (size_t)h * DH_ * T_;

    for (int idx = t; idx < 64 * 16; idx += 128) {
        const int r = idx >> 4, c4 = (idx & 15) * 4;
        float4 v = *reinterpret_cast<const float4*>(
            &g_q[qkb + (size_t)(q0 + r) * D_ + c4]);
        v.x *= 0.125f; v.y *= 0.125f; v.z *= 0.125f; v.w *= 0.125f;
        *reinterpret_cast<float4*>(&Qs[r * FSTR + c4]) = v;
    }
    __syncthreads();

    const int r0 = w * 16 + g;
    const int r1 = r0 + 8;
    uint32_t qh[8][4], ql[8][4];
#pragma unroll
    for (int k = 0; k < 8; ++k) {
        split_tf32(Qs[r0 * FSTR + k * 8 + tg],     qh[k][0], ql[k][0]);
        split_tf32(Qs[r1 * FSTR + k * 8 + tg],     qh[k][1], ql[k][1]);
        split_tf32(Qs[r0 * FSTR + k * 8 + tg + 4], qh[k][2], ql[k][2]);
        split_tf32(Qs[r1 * FSTR + k * 8 + tg + 4], qh[k][3], ql[k][3]);
    }

    float o[8][4];
#pragma unroll
    for (int nf = 0; nf < 8; ++nf)
#pragma unroll
        for (int r = 0; r < 4; ++r) o[nf][r] = 0.f;
    float m0 = -1e30f, m1 = -1e30f, l0 = 0.f, l1 = 0.f;

    const int ntiles = qb + 1;
    for (int kt = 0; kt < ntiles; ++kt) {
        for (int idx = t; idx < 64 * 16; idx += 128) {
            const int r = idx >> 4, c4 = (idx & 15) * 4;
            *reinterpret_cast<float4*>(&Ks[r * FSTR + c4]) =
                *reinterpret_cast<const float4*>(
                    &g_k[qkb + (size_t)(kt * 64 + r) * D_ + c4]);
            *reinterpret_cast<float4*>(&Vt[r * FSTR + c4]) =
                *reinterpret_cast<const float4*>(
                    &g_vT[vtb + (size_t)r * T_ + kt * 64 + c4]);
        }
        __syncthreads();

        float s[8][4];
#pragma unroll
        for (int nf = 0; nf < 8; ++nf)
#pragma unroll
            for (int r = 0; r < 4; ++r) s[nf][r] = 0.f;

#pragma unroll
        for (int k = 0; k < 8; ++k) {
#pragma unroll
            for (int nf = 0; nf < 8; ++nf) {
                const float kv0 = Ks[(nf * 8 + g) * FSTR + k * 8 + tg];
                const float kv1 = Ks[(nf * 8 + g) * FSTR + k * 8 + tg + 4];
                uint32_t kh[2], kl[2];
                split_tf32(kv0, kh[0], kl[0]);
                split_tf32(kv1, kh[1], kl[1]);
                MMA_TF32(s[nf], ql[k], kh);
                MMA_TF32(s[nf], qh[k], kl);
                MMA_TF32(s[nf], qh[k], kh);
            }
        }

        if (kt == qb) {
#pragma unroll
            for (int nf = 0; nf < 8; ++nf) {
                const int c = nf * 8 + 2 * tg;
                if (c     > r0) s[nf][0] = -1e30f;
                if (c + 1 > r0) s[nf][1] = -1e30f;
                if (c     > r1) s[nf][2] = -1e30f;
                if (c + 1 > r1) s[nf][3] = -1e30f;
            }
        }

        float mx0 = -1e30f, mx1 = -1e30f;
#pragma unroll
        for (int nf = 0; nf < 8; ++nf) {
            mx0 = fmaxf(mx0, fmaxf(s[nf][0], s[nf][1]));
            mx1 = fmaxf(mx1, fmaxf(s[nf][2], s[nf][3]));
        }
        mx0 = fmaxf(mx0, __shfl_xor_sync(0xffffffffu, mx0, 1));
        mx0 = fmaxf(mx0, __shfl_xor_sync(0xffffffffu, mx0, 2));
        mx1 = fmaxf(mx1, __shfl_xor_sync(0xffffffffu, mx1, 1));
        mx1 = fmaxf(mx1, __shfl_xor_sync(0xffffffffu, mx1, 2));
        const float mn0 = fmaxf(m0, mx0);
        const float mn1 = fmaxf(m1, mx1);
        const float a0 = __expf(m0 - mn0);
        const float a1 = __expf(m1 - mn1);

        float rs0 = 0.f, rs1 = 0.f;
#pragma unroll
        for (int nf = 0; nf < 8; ++nf) {
            s[nf][0] = __expf(s[nf][0] - mn0); rs0 += s[nf][0];
            s[nf][1] = __expf(s[nf][1] - mn0); rs0 += s[nf][1];
            s[nf][2] = __expf(s[nf][2] - mn1); rs1 += s[nf][2];
            s[nf][3] = __expf(s[nf][3] - mn1); rs1 += s[nf][3];
            o[nf][0] *= a0; o[nf][1] *= a0;
            o[nf][2] *= a1; o[nf][3] *= a1;
        }
        rs0 += __shfl_xor_sync(0xffffffffu, rs0, 1);
        rs0 += __shfl_xor_sync(0xffffffffu, rs0, 2);
        rs1 += __shfl_xor_sync(0xffffffffu, rs1, 1);
        rs1 += __shfl_xor_sync(0xffffffffu, rs1, 2);
        l0 = l0 * a0 + rs0;
        l1 = l1 * a1 + rs1;
        m0 = mn0; m1 = mn1;

        float* Ps = Qs;
#pragma unroll
        for (int nf = 0; nf < 8; ++nf) {
            const int c = nf * 8 + 2 * tg;
            Ps[r0 * FSTR + c]     = rna_tf32(s[nf][0]);
            Ps[r0 * FSTR + c + 1] = rna_tf32(s[nf][1]);
            Ps[r1 * FSTR + c]     = rna_tf32(s[nf][2]);
            Ps[r1 * FSTR + c + 1] = rna_tf32(s[nf][3]);
        }

#pragma unroll
        for (int k = 0; k < 8; ++k) {
            uint32_t pa[4];
            pa[0] = __float_as_uint(Ps[r0 * FSTR + k * 8 + tg]);
            pa[1] = __float_as_uint(Ps[r1 * FSTR + k * 8 + tg]);
            pa[2] = __float_as_uint(Ps[r0 * FSTR + k * 8 + tg + 4]);
            pa[3] = __float_as_uint(Ps[r1 * FSTR + k * 8 + tg + 4]);
#pragma unroll
            for (int nf = 0; nf < 8; ++nf) {
                uint32_t vb[2];
                vb[0] = __float_as_uint(Vt[(nf * 8 + g) * FSTR + k * 8 + tg]);
                vb[1] = __float_as_uint(Vt[(nf * 8 + g) * FSTR + k * 8 + tg + 4]);
                MMA_TF32(o[nf], pa, vb);
            }
        }
        __syncthreads();
    }

    const float i0 = 1.f / l0;
    const float i1 = 1.f / l1;
#pragma unroll
    for (int nf = 0; nf < 8; ++nf) {
        const int c = nf * 8 + 2 * tg;
        float2 v0 = make_float2(o[nf][0] * i0, o[nf][1] * i0);
        float2 v1 = make_float2(o[nf][2] * i1, o[nf][3] * i1);
        *reinterpret_cast<float2*>(&g_ctx[qkb + (size_t)(q0 + r0) * D_ + c]) = v0;
        *reinterpret_cast<float2*>(&g_ctx[qkb + (size_t)(q0 + r1) * D_ + c]) = v1;
    }
}

// ---------------------------------------------------------------------------
extern "C" void kernel_launch(void* const* d_in, const int* in_sizes, int n_in,
                              void* d_out, int out_size) {
    const float* x  = (const float*)d_in[0];
    const float* Wq = (const float*)d_in[1];
    const float* Wk = (const float*)d_in[2];
    const float* Wv = (const float*)d_in[3];
    const float* Wo = (const float*)d_in[4];
    const float* bo = (const float*)d_in[5];
    float* out = (float*)d_out;

    // 1) QKV projections (3xBF16 tensor cores)
    tgemm_qkv<<<dim3(N_ / BN, M_ / BM, 3), 256>>>(x, Wq, Wk, Wv);

    // 2) V transpose (+RNA tf32 rounding)
    transpose_v<<<dim3(T_ / 32, D_ / 32, B_), dim3(32, 8)>>>();

    // 3) Tensor-core causal flash attention
    const int smem = 3 * 64 * FSTR * sizeof(float);
    cudaFuncSetAttribute(flash_attn_tc,
                         cudaFuncAttributeMaxDynamicSharedMemorySize, smem);
    flash_attn_tc<<<dim3(T_ / 64, H_, B_), 128, smem>>>();

    // 4) Output projection (+bias)
    tgemm_out<<<dim3(N_ / BN, M_ / BM), 256>>>(Wo, bo, out);
}

// round 5
// speedup vs baseline: 4.2108x; 1.3382x over previous
#include <cuda_runtime.h>
#include <cuda_bf16.h>
#include <math.h>
#include <stdint.h>

// Problem constants
constexpr int B_  = 4;
constexpr int T_  = 2048;
constexpr int D_  = 1024;
constexpr int H_  = 16;
constexpr int DH_ = 64;
constexpr int M_  = B_ * T_;   // 8192
constexpr int N_  = D_;        // 1024
constexpr int K_  = D_;        // 1024
constexpr int KP_ = K_ / 2;    // 512 k-pairs

// Scratch (device globals: allocation-free per harness rules).
__device__ float    g_q [M_ * D_];
__device__ float    g_k [M_ * D_];
__device__ float    g_v [M_ * D_];
__device__ float    g_vT[M_ * D_];          // [B][D][T]
__device__ uint32_t g_ah[KP_ * M_];          // x packed hi  [K/2][M]
__device__ uint32_t g_al[KP_ * M_];          // x packed lo
__device__ uint32_t g_ch[KP_ * M_];          // ctx packed hi [D/2][M]
__device__ uint32_t g_cl[KP_ * M_];          // ctx packed lo
__device__ uint32_t g_wh[4 * KP_ * N_];      // weights packed hi [z][K/2][N]
__device__ uint32_t g_wl[4 * KP_ * N_];      // weights packed lo

// ---------------------------------------------------------------------------
// Helpers
// ---------------------------------------------------------------------------
#define MMA_TF32(d, a, b)                                                    \
    asm volatile(                                                            \
        "mma.sync.aligned.m16n8k8.row.col.f32.tf32.tf32.f32 "                \
        "{%0,%1,%2,%3}, {%4,%5,%6,%7}, {%8,%9}, {%0,%1,%2,%3};"              \
        : "+f"((d)[0]), "+f"((d)[1]), "+f"((d)[2]), "+f"((d)[3])             \
        : "r"((a)[0]), "r"((a)[1]), "r"((a)[2]), "r"((a)[3]),                \
          "r"((b)[0]), "r"((b)[1]))

#define MMA_BF16(d, a, b)                                                    \
    asm volatile(                                                            \
        "mma.sync.aligned.m16n8k16.row.col.f32.bf16.bf16.f32 "               \
        "{%0,%1,%2,%3}, {%4,%5,%6,%7}, {%8,%9}, {%0,%1,%2,%3};"              \
        : "+f"((d)[0]), "+f"((d)[1]), "+f"((d)[2]), "+f"((d)[3])             \
        : "r"((a)[0]), "r"((a)[1]), "r"((a)[2]), "r"((a)[3]),                \
          "r"((b)[0]), "r"((b)[1]))

#define CP_ASYNC16(dst, src)                                                 \
    asm volatile("cp.async.cg.shared.global [%0], [%1], 16;"                 \
                 :: "r"(dst), "l"(src))
#define CP_COMMIT()  asm volatile("cp.async.commit_group;")
#define CP_WAIT2()   asm volatile("cp.async.wait_group 2;")

__device__ __forceinline__ uint32_t smem_u32(const void* p) {
    return (uint32_t)__cvta_generic_to_shared(p);
}

__device__ __forceinline__ void split_tf32(float x, uint32_t& hi, uint32_t& lo) {
    uint32_t h = __float_as_uint(x) & 0xFFFFE000u;
    hi = h;
    lo = __float_as_uint(x - __uint_as_float(h));
}

__device__ __forceinline__ float rna_tf32(float x) {
    uint32_t u = __float_as_uint(x);
    u = (u + 0x1000u) & 0xFFFFE000u;
    return __uint_as_float(u);
}

// Split (a,b) into bf16 hi pair + bf16 lo-residual pair, packed bf16x2.
__device__ __forceinline__ void packpair_bf16(float a, float b,
                                              uint32_t& h, uint32_t& l) {
    const float ha = __bfloat162float(__float2bfloat16(a));
    const float hb = __bfloat162float(__float2bfloat16(b));
    __nv_bfloat162 H = __floats2bfloat162_rn(ha, hb);
    __nv_bfloat162 L = __floats2bfloat162_rn(a - ha, b - hb);
    h = *reinterpret_cast<uint32_t*>(&H);
    l = *reinterpret_cast<uint32_t*>(&L);
}

// ---------------------------------------------------------------------------
// Packing kernels (run once per graph replay; ~30us total)
// ---------------------------------------------------------------------------
// x [M][K] fp32 -> g_ah/g_al [K/2][M] packed bf16x2 (transpose)
__global__ __launch_bounds__(256)
void pack_x(const float* __restrict__ x) {
    __shared__ uint32_t th[32][33], tl[32][33];
    const int m0  = blockIdx.x * 32;
    const int kp0 = blockIdx.y * 32;
    const int tx  = threadIdx.x;     // 0..31
    const int ty  = threadIdx.y;     // 0..7
#pragma unroll
    for (int i = 0; i < 4; ++i) {
        const int m = ty + i * 8;
        float2 v = *reinterpret_cast<const float2*>(
            &x[(size_t)(m0 + m) * K_ + (size_t)(kp0 + tx) * 2]);
        packpair_bf16(v.x, v.y, th[tx][m], tl[tx][m]);
    }
    __syncthreads();
#pragma unroll
    for (int i = 0; i < 4; ++i) {
        const int kp = ty + i * 8;
        g_ah[(size_t)(kp0 + kp) * M_ + m0 + tx] = th[kp][tx];
        g_al[(size_t)(kp0 + kp) * M_ + m0 + tx] = tl[kp][tx];
    }
}

// W [K][N] fp32 -> packed [K/2][N] (no transpose)
__global__ __launch_bounds__(256)
void pack_w(const float* __restrict__ Wq, const float* __restrict__ Wk,
            const float* __restrict__ Wv, const float* __restrict__ Wo) {
    const int z = blockIdx.z;
    const float* W = (z == 0) ? Wq : (z == 1) ? Wk : (z == 2) ? Wv : Wo;
    const int n  = blockIdx.x * 256 + threadIdx.x;
    const int kp = blockIdx.y;
    const float a = W[(size_t)(2 * kp) * N_ + n];
    const float b = W[(size_t)(2 * kp + 1) * N_ + n];
    uint32_t h, l;
    packpair_bf16(a, b, h, l);
    const size_t o = (size_t)z * KP_ * N_ + (size_t)kp * N_ + n;
    g_wh[o] = h;
    g_wl[o] = l;
}

// ---------------------------------------------------------------------------
// 3xBF16 GEMM, cp.async 4-stage pipeline.
// A packed [K/2][M], B packed [K/2][N]; C fp32 [M][N] (+bias).
// CTA 128x128, BK=16, 8 warps (2M x 4N), warp tile 64x32, 48 MMA / k16.
// ---------------------------------------------------------------------------
constexpr int SSTR   = 136;                 // smem row stride (uint32)
constexpr int STAGES = 4;
constexpr int ST_U32 = 4 * 8 * SSTR;        // uint32 per stage (4352)
constexpr int OFF_AL = 8 * SSTR;
constexpr int OFF_BH = 16 * SSTR;
constexpr int OFF_BL = 24 * SSTR;

__device__ __forceinline__ void tgemm_body(const uint32_t* __restrict__ Ah,
                                           const uint32_t* __restrict__ Al,
                                           const uint32_t* __restrict__ Bh,
                                           const uint32_t* __restrict__ Bl,
                                           float* __restrict__ C,
                                           const float* __restrict__ bias) {
    extern __shared__ uint32_t smp[];
    const uint32_t sb0 = smem_u32(smp);

    const int t    = threadIdx.x;
    const int lane = t & 31;
    const int wid  = t >> 5;
    const int wM   = wid & 1;
    const int wN   = wid >> 1;
    const int g    = lane >> 2;
    const int tg   = lane & 3;

    const int r0 = blockIdx.y * 128;
    const int c0 = blockIdx.x * 128;

    const int crow = t >> 5;          // 0..7  copy row (k-pair)
    const int cc4  = (t & 31) * 4;    // 0..124 copy col (uint32 quad)

    float acc[4][4][4];
#pragma unroll
    for (int i = 0; i < 4; ++i)
#pragma unroll
        for (int j = 0; j < 4; ++j)
#pragma unroll
            for (int r = 0; r < 4; ++r) acc[i][j][r] = 0.f;

    const int NT = K_ / 16;   // 64 k-steps

    // Stage copy lambda: stage kt -> buffer buf
    auto issue = [&](int kt, int buf) {
        const uint32_t db = sb0 + (uint32_t)(buf * ST_U32 + crow * SSTR + cc4) * 4u;
        const size_t kr = (size_t)(kt * 8 + crow);
        CP_ASYNC16(db,               Ah + kr * M_ + r0 + cc4);
        CP_ASYNC16(db + OFF_AL * 4u, Al + kr * M_ + r0 + cc4);
        CP_ASYNC16(db + OFF_BH * 4u, Bh + kr * N_ + c0 + cc4);
        CP_ASYNC16(db + OFF_BL * 4u, Bl + kr * N_ + c0 + cc4);
    };

    // Prologue: fill STAGES-1 stages
#pragma unroll
    for (int s = 0; s < STAGES - 1; ++s) {
        issue(s, s);
        CP_COMMIT();
    }

    for (int kt = 0; kt < NT; ++kt) {
        CP_WAIT2();            // oldest stage (kt) complete
        __syncthreads();

        const uint32_t* sA_hi = smp + (kt % STAGES) * ST_U32;
        const uint32_t* sA_lo = sA_hi + OFF_AL;
        const uint32_t* sB_hi = sA_hi + OFF_BH;
        const uint32_t* sB_lo = sA_hi + OFF_BL;

        uint32_t bh[4][2], bl[4][2];
#pragma unroll
        for (int nf = 0; nf < 4; ++nf) {
            const int cc = wN * 32 + nf * 8 + g;
            bh[nf][0] = sB_hi[tg * SSTR + cc];
            bh[nf][1] = sB_hi[(tg + 4) * SSTR + cc];
            bl[nf][0] = sB_lo[tg * SSTR + cc];
            bl[nf][1] = sB_lo[(tg + 4) * SSTR + cc];
        }
#pragma unroll
        for (int mf = 0; mf < 4; ++mf) {
            const int rb = wM * 64 + mf * 16 + g;
            uint32_t ah[4], al[4];
            ah[0] = sA_hi[tg * SSTR + rb];
            ah[1] = sA_hi[tg * SSTR + rb + 8];
            ah[2] = sA_hi[(tg + 4) * SSTR + rb];
            ah[3] = sA_hi[(tg + 4) * SSTR + rb + 8];
            al[0] = sA_lo[tg * SSTR + rb];
            al[1] = sA_lo[tg * SSTR + rb + 8];
            al[2] = sA_lo[(tg + 4) * SSTR + rb];
            al[3] = sA_lo[(tg + 4) * SSTR + rb + 8];
#pragma unroll
            for (int nf = 0; nf < 4; ++nf) {
                MMA_BF16(acc[mf][nf], al, bh[nf]);
                MMA_BF16(acc[mf][nf], ah, bl[nf]);
                MMA_BF16(acc[mf][nf], ah, bh[nf]);
            }
        }
        __syncthreads();       // all warps done reading before buffer reuse

        const int kn = kt + STAGES - 1;
        if (kn < NT) issue(kn, kn % STAGES);
        CP_COMMIT();
    }

    // Epilogue
#pragma unroll
    for (int mf = 0; mf < 4; ++mf) {
#pragma unroll
        for (int nf = 0; nf < 4; ++nf) {
            const int row = r0 + wM * 64 + mf * 16 + g;
            const int col = c0 + wN * 32 + nf * 8 + 2 * tg;
            float2 v0 = make_float2(acc[mf][nf][0], acc[mf][nf][1]);
            float2 v1 = make_float2(acc[mf][nf][2], acc[mf][nf][3]);
            if (bias) {
                const float b0v = bias[col], b1v = bias[col + 1];
                v0.x += b0v; v0.y += b1v;
                v1.x += b0v; v1.y += b1v;
            }
            *reinterpret_cast<float2*>(&C[(size_t)row * N_ + col])       = v0;
            *reinterpret_cast<float2*>(&C[(size_t)(row + 8) * N_ + col]) = v1;
        }
    }
}

__global__ __launch_bounds__(256, 2)
void tgemm_qkv() {
    const int z = blockIdx.z;
    float* C = (z == 0) ? g_q : (z == 1) ? g_k : g_v;
    tgemm_body(g_ah, g_al,
               g_wh + (size_t)z * KP_ * N_, g_wl + (size_t)z * KP_ * N_,
               C, nullptr);
}

__global__ __launch_bounds__(256, 2)
void tgemm_out(const float* __restrict__ bo, float* __restrict__ out) {
    tgemm_body(g_ch, g_cl,
               g_wh + (size_t)3 * KP_ * N_, g_wl + (size_t)3 * KP_ * N_,
               out, bo);
}

// ---------------------------------------------------------------------------
// V transpose: g_vT[b][d][t] = rna_tf32(g_v[b][t][d]).
// ---------------------------------------------------------------------------
__global__ __launch_bounds__(256)
void transpose_v() {
    __shared__ float tile[32][33];
    const int b  = blockIdx.z;
    const int t0 = blockIdx.x * 32;
    const int d0 = blockIdx.y * 32;
    const int tx = threadIdx.x;
    const int ty = threadIdx.y;
#pragma unroll
    for (int i = 0; i < 32; i += 8)
        tile[ty + i][tx] = g_v[(size_t)b * T_ * D_ + (size_t)(t0 + ty + i) * D_ + d0 + tx];
    __syncthreads();
#pragma unroll
    for (int i = 0; i < 32; i += 8)
        g_vT[(size_t)b * D_ * T_ + (size_t)(d0 + ty + i) * T_ + t0 + tx] =
            rna_tf32(tile[tx][ty + i]);
}

// ---------------------------------------------------------------------------
// Tensor-core causal flash attention. Writes ctx PACKED (hi/lo, [D/2][M]).
// ---------------------------------------------------------------------------
constexpr int FSTR = 68;

__global__ __launch_bounds__(128)
void flash_attn_tc() {
    extern __shared__ float sm[];
    float* Qs = sm;
    float* Ks = sm + 64 * FSTR;
    float* Vt = sm + 2 * 64 * FSTR;

    const int t    = threadIdx.x;
    const int lane = t & 31;
    const int w    = t >> 5;
    const int g    = lane >> 2;
    const int tg   = lane & 3;

    const int qb = (int)gridDim.x - 1 - (int)blockIdx.x;
    const int hh = blockIdx.y;
    const int b  = blockIdx.z;
    const int q0 = qb * 64;
    const size_t qkb = (size_t)b * T_ * D_ + (size_t)hh * DH_;
    const size_t vtb = (size_t)b * D_ * T_ + (size_t)hh * DH_ * T_;

    for (int idx = t; idx < 64 * 16; idx += 128) {
        const int r = idx >> 4, c4 = (idx & 15) * 4;
        float4 v = *reinterpret_cast<const float4*>(
            &g_q[qkb + (size_t)(q0 + r) * D_ + c4]);
        v.x *= 0.125f; v.y *= 0.125f; v.z *= 0.125f; v.w *= 0.125f;
        *reinterpret_cast<float4*>(&Qs[r * FSTR + c4]) = v;
    }
    __syncthreads();

    const int r0 = w * 16 + g;
    const int r1 = r0 + 8;
    uint32_t qh[8][4], ql[8][4];
#pragma unroll
    for (int k = 0; k < 8; ++k) {
        split_tf32(Qs[r0 * FSTR + k * 8 + tg],     qh[k][0], ql[k][0]);
        split_tf32(Qs[r1 * FSTR + k * 8 + tg],     qh[k][1], ql[k][1]);
        split_tf32(Qs[r0 * FSTR + k * 8 + tg + 4], qh[k][2], ql[k][2]);
        split_tf32(Qs[r1 * FSTR + k * 8 + tg + 4], qh[k][3], ql[k][3]);
    }

    float o[8][4];
#pragma unroll
    for (int nf = 0; nf < 8; ++nf)
#pragma unroll
        for (int r = 0; r < 4; ++r) o[nf][r] = 0.f;
    float m0 = -1e30f, m1 = -1e30f, l0 = 0.f, l1 = 0.f;

    const int ntiles = qb + 1;
    for (int kt = 0; kt < ntiles; ++kt) {
        for (int idx = t; idx < 64 * 16; idx += 128) {
            const int r = idx >> 4, c4 = (idx & 15) * 4;
            *reinterpret_cast<float4*>(&Ks[r * FSTR + c4]) =
                *reinterpret_cast<const float4*>(
                    &g_k[qkb + (size_t)(kt * 64 + r) * D_ + c4]);
            *reinterpret_cast<float4*>(&Vt[r * FSTR + c4]) =
                *reinterpret_cast<const float4*>(
                    &g_vT[vtb + (size_t)r * T_ + kt * 64 + c4]);
        }
        __syncthreads();

        float s[8][4];
#pragma unroll
        for (int nf = 0; nf < 8; ++nf)
#pragma unroll
            for (int r = 0; r < 4; ++r) s[nf][r] = 0.f;

#pragma unroll
        for (int k = 0; k < 8; ++k) {
#pragma unroll
            for (int nf = 0; nf < 8; ++nf) {
                const float kv0 = Ks[(nf * 8 + g) * FSTR + k * 8 + tg];
                const float kv1 = Ks[(nf * 8 + g) * FSTR + k * 8 + tg + 4];
                uint32_t kh[2], kl[2];
                split_tf32(kv0, kh[0], kl[0]);
                split_tf32(kv1, kh[1], kl[1]);
                MMA_TF32(s[nf], ql[k], kh);
                MMA_TF32(s[nf], qh[k], kl);
                MMA_TF32(s[nf], qh[k], kh);
            }
        }

        if (kt == qb) {
#pragma unroll
            for (int nf = 0; nf < 8; ++nf) {
                const int c = nf * 8 + 2 * tg;
                if (c     > r0) s[nf][0] = -1e30f;
                if (c + 1 > r0) s[nf][1] = -1e30f;
                if (c     > r1) s[nf][2] = -1e30f;
                if (c + 1 > r1) s[nf][3] = -1e30f;
            }
        }

        float mx0 = -1e30f, mx1 = -1e30f;
#pragma unroll
        for (int nf = 0; nf < 8; ++nf) {
            mx0 = fmaxf(mx0, fmaxf(s[nf][0], s[nf][1]));
            mx1 = fmaxf(mx1, fmaxf(s[nf][2], s[nf][3]));
        }
        mx0 = fmaxf(mx0, __shfl_xor_sync(0xffffffffu, mx0, 1));
        mx0 = fmaxf(mx0, __shfl_xor_sync(0xffffffffu, mx0, 2));
        mx1 = fmaxf(mx1, __shfl_xor_sync(0xffffffffu, mx1, 1));
        mx1 = fmaxf(mx1, __shfl_xor_sync(0xffffffffu, mx1, 2));
        const float mn0 = fmaxf(m0, mx0);
        const float mn1 = fmaxf(m1, mx1);
        const float a0 = __expf(m0 - mn0);
        const float a1 = __expf(m1 - mn1);

        float rs0 = 0.f, rs1 = 0.f;
#pragma unroll
        for (int nf = 0; nf < 8; ++nf) {
            s[nf][0] = __expf(s[nf][0] - mn0); rs0 += s[nf][0];
            s[nf][1] = __expf(s[nf][1] - mn0); rs0 += s[nf][1];
            s[nf][2] = __expf(s[nf][2] - mn1); rs1 += s[nf][2];
            s[nf][3] = __expf(s[nf][3] - mn1); rs1 += s[nf][3];
            o[nf][0] *= a0; o[nf][1] *= a0;
            o[nf][2] *= a1; o[nf][3] *= a1;
        }
        rs0 += __shfl_xor_sync(0xffffffffu, rs0, 1);
        rs0 += __shfl_xor_sync(0xffffffffu, rs0, 2);
        rs1 += __shfl_xor_sync(0xffffffffu, rs1, 1);
        rs1 += __shfl_xor_sync(0xffffffffu, rs1, 2);
        l0 = l0 * a0 + rs0;
        l1 = l1 * a1 + rs1;
        m0 = mn0; m1 = mn1;

        float* Ps = Qs;
#pragma unroll
        for (int nf = 0; nf < 8; ++nf) {
            const int c = nf * 8 + 2 * tg;
            Ps[r0 * FSTR + c]     = rna_tf32(s[nf][0]);
            Ps[r0 * FSTR + c + 1] = rna_tf32(s[nf][1]);
            Ps[r1 * FSTR + c]     = rna_tf32(s[nf][2]);
            Ps[r1 * FSTR + c + 1] = rna_tf32(s[nf][3]);
        }

#pragma unroll
        for (int k = 0; k < 8; ++k) {
            uint32_t pa[4];
            pa[0] = __float_as_uint(Ps[r0 * FSTR + k * 8 + tg]);
            pa[1] = __float_as_uint(Ps[r1 * FSTR + k * 8 + tg]);
            pa[2] = __float_as_uint(Ps[r0 * FSTR + k * 8 + tg + 4]);
            pa[3] = __float_as_uint(Ps[r1 * FSTR + k * 8 + tg + 4]);
#pragma unroll
            for (int nf = 0; nf < 8; ++nf) {
                uint32_t vb[2];
                vb[0] = __float_as_uint(Vt[(nf * 8 + g) * FSTR + k * 8 + tg]);
                vb[1] = __float_as_uint(Vt[(nf * 8 + g) * FSTR + k * 8 + tg + 4]);
                MMA_TF32(o[nf], pa, vb);
            }
        }
        __syncthreads();
    }

    // Normalize + write ctx PACKED: g_ch/g_cl[(col/2)*M + m]
    const float i0 = 1.f / l0;
    const float i1 = 1.f / l1;
    const int mg = b * T_ + q0;
#pragma unroll
    for (int nf = 0; nf < 8; ++nf) {
        const int col = hh * DH_ + nf * 8 + 2 * tg;   // even
        const size_t kp = (size_t)(col >> 1) * M_;
        uint32_t ph, pl;
        packpair_bf16(o[nf][0] * i0, o[nf][1] * i0, ph, pl);
        g_ch[kp + mg + r0] = ph;
        g_cl[kp + mg + r0] = pl;
        packpair_bf16(o[nf][2] * i1, o[nf][3] * i1, ph, pl);
        g_ch[kp + mg + r1] = ph;
        g_cl[kp + mg + r1] = pl;
    }
}

// ---------------------------------------------------------------------------
extern "C" void kernel_launch(void* const* d_in, const int* in_sizes, int n_in,
                              void* d_out, int out_size) {
    const float* x  = (const float*)d_in[0];
    const float* Wq = (const float*)d_in[1];
    const float* Wk = (const float*)d_in[2];
    const float* Wv = (const float*)d_in[3];
    const float* Wo = (const float*)d_in[4];
    const float* bo = (const float*)d_in[5];
    float* out = (float*)d_out;

    // 0) Pack x and weights into bf16 hi/lo
    pack_x<<<dim3(M_ / 32, KP_ / 32), dim3(32, 8)>>>(x);
    pack_w<<<dim3(N_ / 256, KP_, 4), 256>>>(Wq, Wk, Wv, Wo);

    const int gsmem = STAGES * ST_U32 * 4;   // 69,632 B
    cudaFuncSetAttribute(tgemm_qkv,
                         cudaFuncAttributeMaxDynamicSharedMemorySize, gsmem);
    cudaFuncSetAttribute(tgemm_out,
                         cudaFuncAttributeMaxDynamicSharedMemorySize, gsmem);

    // 1) QKV projections
    tgemm_qkv<<<dim3(N_ / 128, M_ / 128, 3), 256, gsmem>>>();

    // 2) V transpose
    transpose_v<<<dim3(T_ / 32, D_ / 32, B_), dim3(32, 8)>>>();

    // 3) Attention (writes packed ctx)
    const int asmem = 3 * 64 * FSTR * sizeof(float);
    cudaFuncSetAttribute(flash_attn_tc,
                         cudaFuncAttributeMaxDynamicSharedMemorySize, asmem);
    flash_attn_tc<<<dim3(T_ / 64, H_, B_), 128, asmem>>>();

    // 4) Output projection (+bias)
    tgemm_out<<<dim3(N_ / 128, M_ / 128), 256, gsmem>>>(bo, out);
}